// round 2
// baseline (speedup 1.0000x reference)
#include <cuda_runtime.h>
#include <cstdint>
#include <cstdio>

// Anchor3DHead: three 1x1 convs over x[B=4, C=384, H=248, W=216].
// Equivalent to out[o, p] = sum_c w[c][o] * x[c][p] (+ bias), o in [0,72),
// with output sections (cls 18 | reg 42 | dir 12) concatenated:
//   out = [ cls (B,18,H,W) | reg (B,42,H,W) | dir (B,12,H,W) ]  (flattened)
//
// Strategy (round 1 baseline): per-pixel GEMV with fused weights in SMEM,
// packed fp32x2 FMAs (fma.rn.f32x2) so the FMA pipe does 2 FMAs/instr.

namespace {
constexpr int Cdim = 384;
constexpr int OCLS = 18, OREG = 42, ODIR = 12;
constexpr int OALL = OCLS + OREG + ODIR;        // 72
constexpr int Hh = 248, Ww = 216;
constexpr int HW = Hh * Ww;                      // 53568
constexpr int Bb = 4;
constexpr int THREADS = 128;
constexpr int WSH_BYTES = Cdim * OALL * 4;       // 110592
}

__global__ void __launch_bounds__(THREADS, 2)
anchor_head_kernel(const float* __restrict__ x,
                   const float* __restrict__ wc, const float* __restrict__ bc,
                   const float* __restrict__ wr, const float* __restrict__ br,
                   const float* __restrict__ wd, const float* __restrict__ bd,
                   float* __restrict__ out)
{
    extern __shared__ float wsh[];   // [Cdim][OALL], row-major, 288 B/row (16B aligned)
    const int tid = threadIdx.x;

    // Cooperative load of fused weight matrix into SMEM (runs once per block;
    // total weight footprint is 110 KB so all re-reads hit L2).
    for (int idx = tid; idx < Cdim * OALL; idx += THREADS) {
        const int c = idx / OALL;
        const int o = idx - c * OALL;
        float v;
        if (o < OCLS)             v = wc[c * OCLS + o];
        else if (o < OCLS + OREG) v = wr[c * OREG + (o - OCLS)];
        else                      v = wd[c * ODIR + (o - OCLS - OREG)];
        wsh[idx] = v;
    }
    __syncthreads();

    const int b = blockIdx.y;
    const int p = blockIdx.x * THREADS + tid;
    if (p >= HW) return;

    const float* xp = x + (size_t)b * Cdim * HW + p;

    // 36 packed accumulators: acc[i] holds outputs (2i, 2i+1) for this pixel.
    unsigned long long acc[OALL / 2];
#pragma unroll
    for (int i = 0; i < OALL / 2; ++i) acc[i] = 0ull;

    unsigned sbase;
    asm("{ .reg .u64 t; cvta.to.shared.u64 t, %1; cvt.u32.u64 %0, t; }"
        : "=r"(sbase) : "l"(wsh));

    // Software-pipelined x loads: prefetch next 4 channels while computing 4.
    float xb[4];
#pragma unroll
    for (int j = 0; j < 4; ++j) xb[j] = xp[(size_t)j * HW];

    for (int c0 = 0; c0 < Cdim; c0 += 4) {
        float xn[4] = {0.f, 0.f, 0.f, 0.f};
        if (c0 + 4 < Cdim) {
#pragma unroll
            for (int j = 0; j < 4; ++j) xn[j] = xp[(size_t)(c0 + 4 + j) * HW];
        }
#pragma unroll
        for (int j = 0; j < 4; ++j) {
            const unsigned xu = __float_as_uint(xb[j]);
            unsigned long long x2;
            asm("mov.b64 %0, {%1, %1};" : "=l"(x2) : "r"(xu));
            const unsigned row = sbase + (unsigned)(c0 + j) * (OALL * 4);
#pragma unroll
            for (int i = 0; i < 18; ++i) {
                unsigned long long w0, w1;
                asm("ld.shared.v2.b64 {%0, %1}, [%2];"
                    : "=l"(w0), "=l"(w1) : "r"(row + i * 16));
                asm("fma.rn.f32x2 %0, %1, %2, %0;"
                    : "+l"(acc[2 * i])     : "l"(x2), "l"(w0));
                asm("fma.rn.f32x2 %0, %1, %2, %0;"
                    : "+l"(acc[2 * i + 1]) : "l"(x2), "l"(w1));
            }
        }
#pragma unroll
        for (int j = 0; j < 4; ++j) xb[j] = xn[j];
    }

    // Unpack accumulators.
    float r[OALL];
#pragma unroll
    for (int i = 0; i < OALL / 2; ++i) {
        unsigned lo, hi;
        asm("mov.b64 {%0, %1}, %2;" : "=r"(lo), "=r"(hi) : "l"(acc[i]));
        r[2 * i]     = __uint_as_float(lo);
        r[2 * i + 1] = __uint_as_float(hi);
    }

    // Epilogue: add bias, write three sections (coalesced over p within warp).
    float* o0 = out + (size_t)b * OCLS * HW + p;
#pragma unroll
    for (int o = 0; o < OCLS; ++o) o0[(size_t)o * HW] = r[o] + bc[o];

    float* o1 = out + (size_t)Bb * OCLS * HW + (size_t)b * OREG * HW + p;
#pragma unroll
    for (int o = 0; o < OREG; ++o) o1[(size_t)o * HW] = r[OCLS + o] + br[o];

    float* o2 = out + (size_t)Bb * (OCLS + OREG) * HW + (size_t)b * ODIR * HW + p;
#pragma unroll
    for (int o = 0; o < ODIR; ++o) o2[(size_t)o * HW] = r[OCLS + OREG + o] + bd[o];
}

extern "C" void kernel_launch(void* const* d_in, const int* in_sizes, int n_in,
                              void* d_out, int out_size)
{
    // Identify inputs robustly by element count (all sizes distinct).
    const float *x = nullptr, *wc = nullptr, *bc = nullptr,
                *wr = nullptr, *br = nullptr, *wd = nullptr, *bd = nullptr;
    for (int i = 0; i < n_in; ++i) {
        const float* ptr = (const float*)d_in[i];
        switch (in_sizes[i]) {
            case Bb * Cdim * HW:  x  = ptr; break;   // 82,280,448
            case Cdim * OCLS:     wc = ptr; break;   // 6912
            case OCLS:            bc = ptr; break;   // 18
            case Cdim * OREG:     wr = ptr; break;   // 16128
            case OREG:            br = ptr; break;   // 42
            case Cdim * ODIR:     wd = ptr; break;   // 4608
            case ODIR:            bd = ptr; break;   // 12
            default: break;
        }
    }

    // Opt-in to >48KB dynamic SMEM (idempotent; not a stream-ordered call).
    cudaFuncSetAttribute(anchor_head_kernel,
                         cudaFuncAttributeMaxDynamicSharedMemorySize, WSH_BYTES);

    dim3 grid((HW + THREADS - 1) / THREADS, Bb);
    anchor_head_kernel<<<grid, THREADS, WSH_BYTES>>>(
        x, wc, bc, wr, br, wd, bd, (float*)d_out);
}

// round 3
// speedup vs baseline: 3.8041x; 3.8041x over previous
#include <cuda_runtime.h>
#include <cstdint>

// Anchor3DHead: out[o,p] = sum_c w[c][o]*x[c][p] + bias[o], o in [0,72),
// x[B=4][C=384][HW=53568]; out sections (cls 18 | reg 42 | dir 12) concatenated.
//
// R2: register-tiled GEMM. Block = 72 outs x 256 pixels, thread = 18 outs x 4
// pixels (36 fp32x2 accumulators). x/w tiles double-buffered in SMEM via
// cp.async. Weights+biases fused once by a pre-kernel into device scratch.

namespace {
constexpr int Cdim = 384;
constexpr int OCLS = 18, OREG = 42, ODIR = 12;
constexpr int OALL = 72;
constexpr int HW = 248 * 216;        // 53568
constexpr int Bb = 4;
constexpr int KC = 16;               // channels per stage
constexpr int NSTAGE = Cdim / KC;    // 24
constexpr int PB = 256;              // pixels per block
constexpr int TPB = 256;             // threads per block
}

__device__ __align__(16) float g_wf[Cdim * OALL];   // fused weights [c][o]
__device__ __align__(16) float g_bias[OALL];

__global__ void fuse_kernel(const float* __restrict__ wc, const float* __restrict__ bc,
                            const float* __restrict__ wr, const float* __restrict__ br,
                            const float* __restrict__ wd, const float* __restrict__ bd)
{
    int i = blockIdx.x * blockDim.x + threadIdx.x;
    if (i < Cdim * OALL) {
        int c = i / OALL, o = i - c * OALL;
        float v;
        if (o < OCLS)             v = wc[c * OCLS + o];
        else if (o < OCLS + OREG) v = wr[c * OREG + (o - OCLS)];
        else                      v = wd[c * ODIR + (o - OCLS - OREG)];
        g_wf[i] = v;
    }
    if (i < OALL)
        g_bias[i] = (i < OCLS) ? bc[i] : (i < OCLS + OREG) ? br[i - OCLS] : bd[i - OCLS - OREG];
}

__device__ __forceinline__ unsigned smem_u32(const void* p) {
    return (unsigned)__cvta_generic_to_shared(p);
}
__device__ __forceinline__ void cp16(unsigned sa, const void* ga) {
    asm volatile("cp.async.cg.shared.global [%0], [%1], 16;\n" :: "r"(sa), "l"(ga));
}

__device__ __forceinline__ size_t out_off(int o, int b) {
    if (o < OCLS) return ((size_t)b * OCLS + o) * HW;
    if (o < OCLS + OREG)
        return (size_t)Bb * OCLS * HW + ((size_t)b * OREG + (o - OCLS)) * HW;
    return (size_t)Bb * (OCLS + OREG) * HW + ((size_t)b * ODIR + (o - OCLS - OREG)) * HW;
}

__global__ void __launch_bounds__(TPB, 2)
anchor_gemm_kernel(const float* __restrict__ x, float* __restrict__ out)
{
    __shared__ __align__(16) float xs[2][KC][PB];    // 32 KB
    __shared__ __align__(16) float ws[2][KC][OALL];  // 9 KB
    __shared__ float bsh[OALL];

    const int tid = threadIdx.x;
    const int og  = tid >> 6;        // 0..3  (18 outputs each)
    const int pg  = tid & 63;        // 0..63 (4 pixels each)
    const int b   = blockIdx.y;
    const int p0  = blockIdx.x * PB;

    if (tid < OALL) bsh[tid] = g_bias[tid];

    const float* xb = x + (size_t)b * Cdim * HW;

    // ---- async stage copy: x[KC][PB] + w[KC][OALL] ----
    auto copy_stage = [&](int s, int buf) {
        const int kbase = s * KC;
        // x: 1024 float4 slots, 4 per thread
#pragma unroll
        for (int i = 0; i < 4; ++i) {
            int f = tid + i * TPB;          // 0..1023
            int row = f >> 6, col = f & 63; // col in float4 units
            int p = p0 + col * 4;
            if (p > HW - 4) p = HW - 4;     // clamp inside row (tail block)
            cp16(smem_u32(&xs[buf][row][col * 4]),
                 xb + (size_t)(kbase + row) * HW + p);
        }
        // w: 1152 floats = 288 float4
        {
            int f = tid;
            cp16(smem_u32(&ws[buf][0][0]) + (unsigned)f * 16,
                 g_wf + (size_t)kbase * OALL + f * 4);
            if (tid < 288 - TPB)
                cp16(smem_u32(&ws[buf][0][0]) + (unsigned)(f + TPB) * 16,
                     g_wf + (size_t)kbase * OALL + (f + TPB) * 4);
        }
    };

    unsigned long long acc[9][4];
#pragma unroll
    for (int i = 0; i < 9; ++i)
#pragma unroll
        for (int j = 0; j < 4; ++j) acc[i][j] = 0ull;

    copy_stage(0, 0);
    asm volatile("cp.async.commit_group;\n");

    for (int s = 0; s < NSTAGE; ++s) {
        const int buf = s & 1;
        if (s + 1 < NSTAGE) {
            copy_stage(s + 1, (s + 1) & 1);
            asm volatile("cp.async.commit_group;\n");
            asm volatile("cp.async.wait_group 1;\n");
        } else {
            asm volatile("cp.async.wait_group 0;\n");
        }
        __syncthreads();

        const unsigned xrow = smem_u32(&xs[buf][0][pg * 4]);
        const unsigned wrow = smem_u32(&ws[buf][0][og * 18]);
#pragma unroll
        for (int k = 0; k < KC; ++k) {
            // 4 pixels of x, duplicated into f32x2 operands
            float4 xv;
            asm("ld.shared.v4.f32 {%0,%1,%2,%3}, [%4];"
                : "=f"(xv.x), "=f"(xv.y), "=f"(xv.z), "=f"(xv.w)
                : "r"(xrow + k * (PB * 4)));
            unsigned long long xd[4];
            asm("mov.b64 %0, {%1, %1};" : "=l"(xd[0]) : "r"(__float_as_uint(xv.x)));
            asm("mov.b64 %0, {%1, %1};" : "=l"(xd[1]) : "r"(__float_as_uint(xv.y)));
            asm("mov.b64 %0, {%1, %1};" : "=l"(xd[2]) : "r"(__float_as_uint(xv.z)));
            asm("mov.b64 %0, {%1, %1};" : "=l"(xd[3]) : "r"(__float_as_uint(xv.w)));
            // 9 weight pairs (broadcast across warp -> conflict-free)
#pragma unroll
            for (int i = 0; i < 9; ++i) {
                unsigned long long wv;
                asm("ld.shared.b64 %0, [%1];"
                    : "=l"(wv) : "r"(wrow + k * (OALL * 4) + i * 8));
#pragma unroll
                for (int j = 0; j < 4; ++j)
                    asm("fma.rn.f32x2 %0, %1, %2, %0;"
                        : "+l"(acc[i][j]) : "l"(xd[j]), "l"(wv));
            }
        }
        __syncthreads();
    }

    // ---- epilogue: unpack, add bias, store ----
    float rr[18][4];
#pragma unroll
    for (int i = 0; i < 9; ++i)
#pragma unroll
        for (int j = 0; j < 4; ++j) {
            unsigned lo, hi;
            asm("mov.b64 {%0, %1}, %2;" : "=r"(lo), "=r"(hi) : "l"(acc[i][j]));
            rr[2 * i][j]     = __uint_as_float(lo);
            rr[2 * i + 1][j] = __uint_as_float(hi);
        }

    const int pbase = p0 + pg * 4;
    const bool full = (p0 + PB <= HW);
#pragma unroll
    for (int o2 = 0; o2 < 18; ++o2) {
        const int o = og * 18 + o2;
        const float bv = bsh[o];
        float* op = out + out_off(o, b);
        if (full) {
            float4 v = make_float4(rr[o2][0] + bv, rr[o2][1] + bv,
                                   rr[o2][2] + bv, rr[o2][3] + bv);
            *reinterpret_cast<float4*>(op + pbase) = v;
        } else {
#pragma unroll
            for (int j = 0; j < 4; ++j)
                if (pbase + j < HW) op[pbase + j] = rr[o2][j] + bv;
        }
    }
}

extern "C" void kernel_launch(void* const* d_in, const int* in_sizes, int n_in,
                              void* d_out, int out_size)
{
    const float *x = nullptr, *wc = nullptr, *bc = nullptr,
                *wr = nullptr, *br = nullptr, *wd = nullptr, *bd = nullptr;
    for (int i = 0; i < n_in; ++i) {
        const float* ptr = (const float*)d_in[i];
        switch (in_sizes[i]) {
            case Bb * Cdim * HW:  x  = ptr; break;
            case Cdim * OCLS:     wc = ptr; break;
            case OCLS:            bc = ptr; break;
            case Cdim * OREG:     wr = ptr; break;
            case OREG:            br = ptr; break;
            case Cdim * ODIR:     wd = ptr; break;
            case ODIR:            bd = ptr; break;
            default: break;
        }
    }

    fuse_kernel<<<(Cdim * OALL + 255) / 256, 256>>>(wc, bc, wr, br, wd, bd);

    dim3 grid((HW + PB - 1) / PB, Bb);   // (210, 4)
    anchor_gemm_kernel<<<grid, TPB>>>(x, (float*)d_out);
}

// round 5
// speedup vs baseline: 4.5742x; 1.2024x over previous
#include <cuda_runtime.h>
#include <cstdint>

// Anchor3DHead as tiled GEMM on the tensor pipe (mma.sync m16n8k8 tf32).
// out[o,p] = sum_c w[c][o]*x[c][p] + bias[o], o in [0,72), p in [0, HW) per batch.
// Block: 256 px x 72 outs. Warp: 32 px x 72 outs (2 Mtiles x 9 Ntiles).
// x/w tiles double-buffered in SMEM via cp.async; weights pre-rounded to tf32.

namespace {
constexpr int Cdim = 384;
constexpr int OCLS = 18, OREG = 42, ODIR = 12;
constexpr int OALL = 72;
constexpr int HW   = 248 * 216;   // 53568
constexpr int Bb   = 4;
constexpr int KC   = 16;          // channels per stage
constexpr int NSTAGE = Cdim / KC; // 24
constexpr int PB   = 256;         // pixels per block
constexpr int TPB  = 256;
constexpr int XSP  = 260;         // padded x row stride (floats)
constexpr int WSP  = 100;         // padded w row stride (floats)
}

__device__ __align__(16) float g_wf[Cdim * OALL];  // [c][o], tf32-rounded bits
__device__ __align__(16) float g_bias[OALL];

__global__ void fuse_kernel(const float* __restrict__ wc, const float* __restrict__ bc,
                            const float* __restrict__ wr, const float* __restrict__ br,
                            const float* __restrict__ wd, const float* __restrict__ bd)
{
    int i = blockIdx.x * blockDim.x + threadIdx.x;
    if (i < Cdim * OALL) {
        int c = i / OALL, o = i - c * OALL;
        float v;
        if (o < OCLS)             v = wc[c * OCLS + o];
        else if (o < OCLS + OREG) v = wr[c * OREG + (o - OCLS)];
        else                      v = wd[c * ODIR + (o - OCLS - OREG)];
        unsigned u;
        asm("cvt.rna.tf32.f32 %0, %1;" : "=r"(u) : "f"(v));
        g_wf[i] = __uint_as_float(u);
    }
    if (i < OALL)
        g_bias[i] = (i < OCLS) ? bc[i] : (i < OCLS + OREG) ? br[i - OCLS]
                                                           : bd[i - OCLS - OREG];
}

__device__ __forceinline__ unsigned smem_u32(const void* p) {
    return (unsigned)__cvta_generic_to_shared(p);
}
__device__ __forceinline__ void cp16(unsigned sa, const void* ga) {
    asm volatile("cp.async.cg.shared.global [%0], [%1], 16;\n" :: "r"(sa), "l"(ga));
}

__device__ __forceinline__ size_t out_off(int o, int b) {
    if (o < OCLS) return ((size_t)b * OCLS + o) * HW;
    if (o < OCLS + OREG)
        return (size_t)Bb * OCLS * HW + ((size_t)b * OREG + (o - OCLS)) * HW;
    return (size_t)Bb * (OCLS + OREG) * HW + ((size_t)b * ODIR + (o - OCLS - OREG)) * HW;
}

__device__ __forceinline__ void mma_tf32(float* c, const unsigned* a,
                                         unsigned b0, unsigned b1) {
    asm volatile(
        "mma.sync.aligned.m16n8k8.row.col.f32.tf32.tf32.f32 "
        "{%0,%1,%2,%3}, {%4,%5,%6,%7}, {%8,%9}, {%0,%1,%2,%3};"
        : "+f"(c[0]), "+f"(c[1]), "+f"(c[2]), "+f"(c[3])
        : "r"(a[0]), "r"(a[1]), "r"(a[2]), "r"(a[3]), "r"(b0), "r"(b1));
}

__global__ void __launch_bounds__(TPB, 2)
anchor_mma_kernel(const float* __restrict__ x, float* __restrict__ out)
{
    __shared__ __align__(16) float xs[2][KC][XSP];  // 33.3 KB
    __shared__ __align__(16) float ws[2][KC][WSP];  // 12.8 KB
    __shared__ float bsh[OALL];

    const int tid  = threadIdx.x;
    const int warp = tid >> 5;
    const int lane = tid & 31;
    const int g    = lane >> 2;   // group 0..7
    const int tig  = lane & 3;    // thread-in-group 0..3
    const int b    = blockIdx.y;
    const int p0   = blockIdx.x * PB;

    if (tid < OALL) bsh[tid] = g_bias[tid];

    const float* xb = x + (size_t)b * Cdim * HW;

    auto copy_stage = [&](int s, int buf) {
        const int kbase = s * KC;
        // x tile: KC x PB floats = 1024 float4, 4 per thread
#pragma unroll
        for (int i = 0; i < 4; ++i) {
            int f = tid + i * TPB;
            int row = f >> 6, col = f & 63;           // col in float4 units
            int p = p0 + col * 4;
            if (p > HW - 4) p = HW - 4;               // clamp for tail tile
            cp16(smem_u32(&xs[buf][row][col * 4]),
                 xb + (size_t)(kbase + row) * HW + p);
        }
        // w tile: KC x OALL floats = 288 float4
        for (int f = tid; f < KC * (OALL / 4); f += TPB) {
            int row = f / (OALL / 4), col = f - row * (OALL / 4);
            cp16(smem_u32(&ws[buf][row][col * 4]),
                 g_wf + (size_t)(kbase + row) * OALL + col * 4);
        }
    };

    float acc[2][9][4];
#pragma unroll
    for (int mt = 0; mt < 2; ++mt)
#pragma unroll
        for (int nt = 0; nt < 9; ++nt)
#pragma unroll
            for (int i = 0; i < 4; ++i) acc[mt][nt][i] = 0.f;

    copy_stage(0, 0);
    asm volatile("cp.async.commit_group;\n");

    const int pw0 = warp * 32;   // warp's pixel offset within block tile

    for (int s = 0; s < NSTAGE; ++s) {
        const int buf = s & 1;
        if (s + 1 < NSTAGE) {
            copy_stage(s + 1, (s + 1) & 1);
            asm volatile("cp.async.commit_group;\n");
            asm volatile("cp.async.wait_group 1;\n");
        } else {
            asm volatile("cp.async.wait_group 0;\n");
        }
        __syncthreads();

#pragma unroll
        for (int ks = 0; ks < KC / 8; ++ks) {
            const int k0 = ks * 8;
            // A fragments: 2 Mtiles x 4 regs (tf32)
            unsigned ua[2][4];
#pragma unroll
            for (int mt = 0; mt < 2; ++mt) {
                const int pw = pw0 + mt * 16;
                float a0 = xs[buf][k0 + tig][pw + g];
                float a1 = xs[buf][k0 + tig][pw + g + 8];
                float a2 = xs[buf][k0 + tig + 4][pw + g];
                float a3 = xs[buf][k0 + tig + 4][pw + g + 8];
                asm("cvt.rna.tf32.f32 %0, %1;" : "=r"(ua[mt][0]) : "f"(a0));
                asm("cvt.rna.tf32.f32 %0, %1;" : "=r"(ua[mt][1]) : "f"(a1));
                asm("cvt.rna.tf32.f32 %0, %1;" : "=r"(ua[mt][2]) : "f"(a2));
                asm("cvt.rna.tf32.f32 %0, %1;" : "=r"(ua[mt][3]) : "f"(a3));
            }
            // B fragments + MMAs
#pragma unroll
            for (int nt = 0; nt < 9; ++nt) {
                unsigned b0 = __float_as_uint(ws[buf][k0 + tig][nt * 8 + g]);
                unsigned b1 = __float_as_uint(ws[buf][k0 + 4 + tig][nt * 8 + g]);
                mma_tf32(acc[0][nt], ua[0], b0, b1);
                mma_tf32(acc[1][nt], ua[1], b0, b1);
            }
        }
        __syncthreads();
    }

    // Epilogue: c0:(g, 2t), c1:(g, 2t+1), c2:(g+8, 2t), c3:(g+8, 2t+1)
#pragma unroll
    for (int mt = 0; mt < 2; ++mt) {
        const int plo = p0 + pw0 + mt * 16 + g;
        const int phi = plo + 8;
        const bool vlo = plo < HW, vhi = phi < HW;
#pragma unroll
        for (int nt = 0; nt < 9; ++nt) {
            const int o0 = nt * 8 + 2 * tig;
            const float bv0 = bsh[o0], bv1 = bsh[o0 + 1];
            float* q0 = out + out_off(o0, b);
            float* q1 = out + out_off(o0 + 1, b);
            if (vlo) {
                q0[plo] = acc[mt][nt][0] + bv0;
                q1[plo] = acc[mt][nt][1] + bv1;
            }
            if (vhi) {
                q0[phi] = acc[mt][nt][2] + bv0;
                q1[phi] = acc[mt][nt][3] + bv1;
            }
        }
    }
}

extern "C" void kernel_launch(void* const* d_in, const int* in_sizes, int n_in,
                              void* d_out, int out_size)
{
    const float *x = nullptr, *wc = nullptr, *bc = nullptr,
                *wr = nullptr, *br = nullptr, *wd = nullptr, *bd = nullptr;
    for (int i = 0; i < n_in; ++i) {
        const float* ptr = (const float*)d_in[i];
        switch (in_sizes[i]) {
            case Bb * Cdim * HW:  x  = ptr; break;
            case Cdim * OCLS:     wc = ptr; break;
            case OCLS:            bc = ptr; break;
            case Cdim * OREG:     wr = ptr; break;
            case OREG:            br = ptr; break;
            case Cdim * ODIR:     wd = ptr; break;
            case ODIR:            bd = ptr; break;
            default: break;
        }
    }

    fuse_kernel<<<(Cdim * OALL + 255) / 256, 256>>>(wc, bc, wr, br, wd, bd);

    dim3 grid((HW + PB - 1) / PB, Bb);   // (210, 4)
    anchor_mma_kernel<<<grid, TPB>>>(x, (float*)d_out);
}

// round 6
// speedup vs baseline: 8.5320x; 1.8652x over previous
#include <cuda_runtime.h>
#include <cstdint>

// Anchor3DHead as tiled GEMM on the tensor pipe (mma.sync m16n8k8 tf32).
// out[o,p] = sum_c w[c][o]*x[c][p] + bias[o], o in [0,72), p per batch in [0,HW).
// Block: 256 px x 72 outs, 4 warps; warp: 64 px x 72 outs (4 Mtiles x 9 Ntiles).
// B fragments stored pair-permuted so each (b0,b1) is one LDS.64.

namespace {
constexpr int Cdim = 384;
constexpr int OCLS = 18, OREG = 42, ODIR = 12;
constexpr int OALL = 72;
constexpr int HW   = 248 * 216;   // 53568
constexpr int Bb   = 4;
constexpr int KC   = 16;          // channels per stage
constexpr int NSTAGE = Cdim / KC; // 24
constexpr int PB   = 256;         // pixels per block
constexpr int TPB  = 128;         // 4 warps
constexpr int XSP  = 260;         // padded x row stride (floats)
constexpr int NKS  = Cdim / 8;    // 48 ksteps total
}

// Weights, fused + tf32-rounded + pair-permuted: g_wq[k/8][o][kin'] where
// slot 2*t holds k%8==t and slot 2*t+1 holds k%8==t+4  (t in 0..3).
__device__ __align__(16) float g_wq[NKS * OALL * 8];
__device__ __align__(16) float g_bias[OALL];

__global__ void fuse_kernel(const float* __restrict__ wc, const float* __restrict__ bc,
                            const float* __restrict__ wr, const float* __restrict__ br,
                            const float* __restrict__ wd, const float* __restrict__ bd)
{
    int i = blockIdx.x * blockDim.x + threadIdx.x;   // i = c*OALL + o
    if (i < Cdim * OALL) {
        int c = i / OALL, o = i - c * OALL;
        float v;
        if (o < OCLS)             v = wc[c * OCLS + o];
        else if (o < OCLS + OREG) v = wr[c * OREG + (o - OCLS)];
        else                      v = wd[c * ODIR + (o - OCLS - OREG)];
        unsigned u;
        asm("cvt.rna.tf32.f32 %0, %1;" : "=r"(u) : "f"(v));
        int ks = c >> 3, kin = c & 7;
        int slot = (kin < 4) ? (2 * kin) : (2 * (kin - 4) + 1);
        g_wq[(ks * OALL + o) * 8 + slot] = __uint_as_float(u);
    }
    if (i < OALL)
        g_bias[i] = (i < OCLS) ? bc[i] : (i < OCLS + OREG) ? br[i - OCLS]
                                                           : bd[i - OCLS - OREG];
}

__device__ __forceinline__ unsigned smem_u32(const void* p) {
    return (unsigned)__cvta_generic_to_shared(p);
}
__device__ __forceinline__ void cp16(unsigned sa, const void* ga) {
    asm volatile("cp.async.cg.shared.global [%0], [%1], 16;\n" :: "r"(sa), "l"(ga));
}

__device__ __forceinline__ size_t out_off(int o, int b) {
    if (o < OCLS) return ((size_t)b * OCLS + o) * HW;
    if (o < OCLS + OREG)
        return (size_t)Bb * OCLS * HW + ((size_t)b * OREG + (o - OCLS)) * HW;
    return (size_t)Bb * (OCLS + OREG) * HW + ((size_t)b * ODIR + (o - OCLS - OREG)) * HW;
}

__device__ __forceinline__ void mma_tf32(float* c, const unsigned* a,
                                         unsigned b0, unsigned b1) {
    asm volatile(
        "mma.sync.aligned.m16n8k8.row.col.f32.tf32.tf32.f32 "
        "{%0,%1,%2,%3}, {%4,%5,%6,%7}, {%8,%9}, {%0,%1,%2,%3};"
        : "+f"(c[0]), "+f"(c[1]), "+f"(c[2]), "+f"(c[3])
        : "r"(a[0]), "r"(a[1]), "r"(a[2]), "r"(a[3]), "r"(b0), "r"(b1));
}

__global__ void __launch_bounds__(TPB, 2)
anchor_mma_kernel(const float* __restrict__ x, float* __restrict__ out)
{
    __shared__ __align__(16) float xs[2][KC][XSP];          // 33.3 KB
    __shared__ __align__(16) float wq[2][2][OALL][8];       // 9.2 KB
    __shared__ float bsh[OALL];

    const int tid  = threadIdx.x;
    const int warp = tid >> 5;
    const int lane = tid & 31;
    const int g    = lane >> 2;   // 0..7
    const int tig  = lane & 3;    // 0..3
    const int b    = blockIdx.y;
    const int p0   = blockIdx.x * PB;

    if (tid < OALL) bsh[tid] = g_bias[tid];

    const float* xb = x + (size_t)b * Cdim * HW;

    auto copy_stage = [&](int s, int buf) {
        const int kbase = s * KC;
        // x tile: KC x PB floats = 1024 float4, 8 per thread
#pragma unroll
        for (int i = 0; i < 8; ++i) {
            int f = tid + i * TPB;
            int row = f >> 6, col = f & 63;           // col in float4 units
            int p = p0 + col * 4;
            if (p > HW - 4) p = HW - 4;               // clamp for tail tile
            cp16(smem_u32(&xs[buf][row][col * 4]),
                 xb + (size_t)(kbase + row) * HW + p);
        }
        // w tile: 2 ksteps x OALL x 8 floats = 288 float4
        const float* wsrc = g_wq + (size_t)(2 * s) * OALL * 8;
        unsigned wdst = smem_u32(&wq[buf][0][0][0]);
#pragma unroll
        for (int i = 0; i < 2; ++i) {
            int f = tid + i * TPB;
            cp16(wdst + (unsigned)f * 16, wsrc + f * 4);
        }
        if (tid < 288 - 2 * TPB)
            cp16(wdst + (unsigned)(tid + 2 * TPB) * 16, wsrc + (tid + 2 * TPB) * 4);
    };

    float acc[4][9][4];
#pragma unroll
    for (int mt = 0; mt < 4; ++mt)
#pragma unroll
        for (int nt = 0; nt < 9; ++nt)
#pragma unroll
            for (int i = 0; i < 4; ++i) acc[mt][nt][i] = 0.f;

    copy_stage(0, 0);
    asm volatile("cp.async.commit_group;\n");

    const int pw0 = warp * 64;   // warp's pixel offset within block tile

    for (int s = 0; s < NSTAGE; ++s) {
        const int buf = s & 1;
        if (s + 1 < NSTAGE) {
            copy_stage(s + 1, (s + 1) & 1);
            asm volatile("cp.async.commit_group;\n");
            asm volatile("cp.async.wait_group 1;\n");
        } else {
            asm volatile("cp.async.wait_group 0;\n");
        }
        __syncthreads();

#pragma unroll
        for (int ks = 0; ks < KC / 8; ++ks) {
            const int k0 = ks * 8;
            // A fragments: 4 Mtiles x 4 regs (tf32)
            unsigned ua[4][4];
#pragma unroll
            for (int mt = 0; mt < 4; ++mt) {
                const int pw = pw0 + mt * 16;
                float a0 = xs[buf][k0 + tig][pw + g];
                float a1 = xs[buf][k0 + tig][pw + g + 8];
                float a2 = xs[buf][k0 + tig + 4][pw + g];
                float a3 = xs[buf][k0 + tig + 4][pw + g + 8];
                asm("cvt.rna.tf32.f32 %0, %1;" : "=r"(ua[mt][0]) : "f"(a0));
                asm("cvt.rna.tf32.f32 %0, %1;" : "=r"(ua[mt][1]) : "f"(a1));
                asm("cvt.rna.tf32.f32 %0, %1;" : "=r"(ua[mt][2]) : "f"(a2));
                asm("cvt.rna.tf32.f32 %0, %1;" : "=r"(ua[mt][3]) : "f"(a3));
            }
            // B fragment pairs via LDS.64 + 4 MMAs each
            const unsigned wrow = smem_u32(&wq[buf][ks][0][0]) + (unsigned)tig * 8;
#pragma unroll
            for (int nt = 0; nt < 9; ++nt) {
                unsigned b0, b1;
                asm("ld.shared.v2.b32 {%0, %1}, [%2];"
                    : "=r"(b0), "=r"(b1)
                    : "r"(wrow + (unsigned)(nt * 8 + g) * 32));
                mma_tf32(acc[0][nt], ua[0], b0, b1);
                mma_tf32(acc[1][nt], ua[1], b0, b1);
                mma_tf32(acc[2][nt], ua[2], b0, b1);
                mma_tf32(acc[3][nt], ua[3], b0, b1);
            }
        }
        __syncthreads();
    }

    // Epilogue: c0:(g, 2t), c1:(g, 2t+1), c2:(g+8, 2t), c3:(g+8, 2t+1)
#pragma unroll
    for (int mt = 0; mt < 4; ++mt) {
        const int plo = p0 + pw0 + mt * 16 + g;
        const int phi = plo + 8;
        const bool vlo = plo < HW, vhi = phi < HW;
#pragma unroll
        for (int nt = 0; nt < 9; ++nt) {
            const int o0 = nt * 8 + 2 * tig;
            const float bv0 = bsh[o0], bv1 = bsh[o0 + 1];
            float* q0 = out + out_off(o0, b);
            float* q1 = out + out_off(o0 + 1, b);
            if (vlo) {
                q0[plo] = acc[mt][nt][0] + bv0;
                q1[plo] = acc[mt][nt][1] + bv1;
            }
            if (vhi) {
                q0[phi] = acc[mt][nt][2] + bv0;
                q1[phi] = acc[mt][nt][3] + bv1;
            }
        }
    }
}

extern "C" void kernel_launch(void* const* d_in, const int* in_sizes, int n_in,
                              void* d_out, int out_size)
{
    const float *x = nullptr, *wc = nullptr, *bc = nullptr,
                *wr = nullptr, *br = nullptr, *wd = nullptr, *bd = nullptr;
    for (int i = 0; i < n_in; ++i) {
        const float* ptr = (const float*)d_in[i];
        switch (in_sizes[i]) {
            case Bb * Cdim * HW:  x  = ptr; break;
            case Cdim * OCLS:     wc = ptr; break;
            case OCLS:            bc = ptr; break;
            case Cdim * OREG:     wr = ptr; break;
            case OREG:            br = ptr; break;
            case Cdim * ODIR:     wd = ptr; break;
            case ODIR:            bd = ptr; break;
            default: break;
        }
    }

    fuse_kernel<<<(Cdim * OALL + 255) / 256, 256>>>(wc, bc, wr, br, wd, bd);

    dim3 grid((HW + PB - 1) / PB, Bb);   // (210, 4)
    anchor_mma_kernel<<<grid, TPB>>>(x, (float*)d_out);
}

// round 7
// speedup vs baseline: 9.0770x; 1.0639x over previous
#include <cuda_runtime.h>
#include <cstdint>

// Anchor3DHead as tiled GEMM on the tensor pipe (mma.sync m16n8k8 tf32).
// out[o,p] = sum_c w[c][o]*x[c][p] + bias[o], o in [0,72), p per batch in [0,HW).
// Block: 256 px x 72 outs, 4 warps; warp: 64 px x 72 outs (4 Mtiles x 9 Ntiles).
// R6: 4-stage cp.async pipeline (quad buffer) in dynamic SMEM for DRAM MLP.

namespace {
constexpr int Cdim = 384;
constexpr int OCLS = 18, OREG = 42, ODIR = 12;
constexpr int OALL = 72;
constexpr int HW   = 248 * 216;   // 53568
constexpr int Bb   = 4;
constexpr int KC   = 16;          // channels per stage
constexpr int NSTAGE = Cdim / KC; // 24
constexpr int NBUF = 4;           // pipeline depth
constexpr int PB   = 256;         // pixels per block
constexpr int TPB  = 128;         // 4 warps
constexpr int XSP  = 260;         // padded x row stride (floats)
constexpr int NKS  = Cdim / 8;    // 48 ksteps total

// dynamic SMEM layout (floats)
constexpr int XS_ELEMS  = NBUF * KC * XSP;        // 16640
constexpr int WQ_ELEMS  = NBUF * 2 * OALL * 8;    // 4608
constexpr int OFF_WQ    = XS_ELEMS;               // after xs
constexpr int OFF_BS    = XS_ELEMS + WQ_ELEMS;    // bias
constexpr int SM_BYTES  = (OFF_BS + OALL) * 4;    // 85,280 B
}

// Weights, fused + tf32-rounded + pair-permuted: g_wq[k/8][o][kin'] where
// slot 2*t holds k%8==t and slot 2*t+1 holds k%8==t+4  (t in 0..3).
__device__ __align__(16) float g_wq[NKS * OALL * 8];
__device__ __align__(16) float g_bias[OALL];

__global__ void fuse_kernel(const float* __restrict__ wc, const float* __restrict__ bc,
                            const float* __restrict__ wr, const float* __restrict__ br,
                            const float* __restrict__ wd, const float* __restrict__ bd)
{
    int i = blockIdx.x * blockDim.x + threadIdx.x;   // i = c*OALL + o
    if (i < Cdim * OALL) {
        int c = i / OALL, o = i - c * OALL;
        float v;
        if (o < OCLS)             v = wc[c * OCLS + o];
        else if (o < OCLS + OREG) v = wr[c * OREG + (o - OCLS)];
        else                      v = wd[c * ODIR + (o - OCLS - OREG)];
        unsigned u;
        asm("cvt.rna.tf32.f32 %0, %1;" : "=r"(u) : "f"(v));
        int ks = c >> 3, kin = c & 7;
        int slot = (kin < 4) ? (2 * kin) : (2 * (kin - 4) + 1);
        g_wq[(ks * OALL + o) * 8 + slot] = __uint_as_float(u);
    }
    if (i < OALL)
        g_bias[i] = (i < OCLS) ? bc[i] : (i < OCLS + OREG) ? br[i - OCLS]
                                                           : bd[i - OCLS - OREG];
}

__device__ __forceinline__ unsigned smem_u32(const void* p) {
    return (unsigned)__cvta_generic_to_shared(p);
}
__device__ __forceinline__ void cp16(unsigned sa, const void* ga) {
    asm volatile("cp.async.cg.shared.global [%0], [%1], 16;\n" :: "r"(sa), "l"(ga));
}

__device__ __forceinline__ size_t out_off(int o, int b) {
    if (o < OCLS) return ((size_t)b * OCLS + o) * HW;
    if (o < OCLS + OREG)
        return (size_t)Bb * OCLS * HW + ((size_t)b * OREG + (o - OCLS)) * HW;
    return (size_t)Bb * (OCLS + OREG) * HW + ((size_t)b * ODIR + (o - OCLS - OREG)) * HW;
}

__device__ __forceinline__ void mma_tf32(float* c, const unsigned* a,
                                         unsigned b0, unsigned b1) {
    asm volatile(
        "mma.sync.aligned.m16n8k8.row.col.f32.tf32.tf32.f32 "
        "{%0,%1,%2,%3}, {%4,%5,%6,%7}, {%8,%9}, {%0,%1,%2,%3};"
        : "+f"(c[0]), "+f"(c[1]), "+f"(c[2]), "+f"(c[3])
        : "r"(a[0]), "r"(a[1]), "r"(a[2]), "r"(a[3]), "r"(b0), "r"(b1));
}

__global__ void __launch_bounds__(TPB, 2)
anchor_mma_kernel(const float* __restrict__ x, float* __restrict__ out)
{
    extern __shared__ __align__(16) float sm[];
    float* xs  = sm;                 // [NBUF][KC][XSP]
    float* wqs = sm + OFF_WQ;        // [NBUF][2][OALL][8]
    float* bsh = sm + OFF_BS;        // [OALL]

    const int tid  = threadIdx.x;
    const int warp = tid >> 5;
    const int lane = tid & 31;
    const int g    = lane >> 2;   // 0..7
    const int tig  = lane & 3;    // 0..3
    const int b    = blockIdx.y;
    const int p0   = blockIdx.x * PB;

    if (tid < OALL) bsh[tid] = g_bias[tid];

    const float* xb = x + (size_t)b * Cdim * HW;

    auto copy_stage = [&](int s) {
        const int buf = s & (NBUF - 1);
        const int kbase = s * KC;
        float* xsb = xs + buf * (KC * XSP);
        // x tile: KC x PB floats = 1024 float4, 8 per thread
#pragma unroll
        for (int i = 0; i < 8; ++i) {
            int f = tid + i * TPB;
            int row = f >> 6, col = f & 63;           // col in float4 units
            int p = p0 + col * 4;
            if (p > HW - 4) p = HW - 4;               // clamp for tail tile
            cp16(smem_u32(xsb + row * XSP + col * 4),
                 xb + (size_t)(kbase + row) * HW + p);
        }
        // w tile: 2 ksteps x OALL x 8 floats = 288 float4
        const float* wsrc = g_wq + (size_t)(2 * s) * OALL * 8;
        unsigned wdst = smem_u32(wqs + buf * (2 * OALL * 8));
#pragma unroll
        for (int i = 0; i < 2; ++i) {
            int f = tid + i * TPB;
            cp16(wdst + (unsigned)f * 16, wsrc + f * 4);
        }
        if (tid < 288 - 2 * TPB)
            cp16(wdst + (unsigned)(tid + 2 * TPB) * 16, wsrc + (tid + 2 * TPB) * 4);
    };

    float acc[4][9][4];
#pragma unroll
    for (int mt = 0; mt < 4; ++mt)
#pragma unroll
        for (int nt = 0; nt < 9; ++nt)
#pragma unroll
            for (int i = 0; i < 4; ++i) acc[mt][nt][i] = 0.f;

    // Prologue: fill NBUF-1 stages.
#pragma unroll
    for (int s = 0; s < NBUF - 1; ++s) {
        copy_stage(s);
        asm volatile("cp.async.commit_group;\n");
    }

    const int pw0 = warp * 64;   // warp's pixel offset within block tile

    for (int s = 0; s < NSTAGE; ++s) {
        const int buf = s & (NBUF - 1);
        if (s + NBUF - 1 < NSTAGE) {
            copy_stage(s + NBUF - 1);
            asm volatile("cp.async.commit_group;\n");
            asm volatile("cp.async.wait_group %0;\n" :: "n"(NBUF - 1));
        } else {
            // tail: decreasing pending count so stage s is complete
            const int rem = NSTAGE - 1 - s;   // groups still pending after wait
            if (rem == 2)      asm volatile("cp.async.wait_group 2;\n");
            else if (rem == 1) asm volatile("cp.async.wait_group 1;\n");
            else               asm volatile("cp.async.wait_group 0;\n");
        }
        __syncthreads();

        const float* xsb = xs + buf * (KC * XSP);
        const float* wqb = wqs + buf * (2 * OALL * 8);

#pragma unroll
        for (int ks = 0; ks < KC / 8; ++ks) {
            const int k0 = ks * 8;
            // A fragments: 4 Mtiles x 4 regs (tf32)
            unsigned ua[4][4];
#pragma unroll
            for (int mt = 0; mt < 4; ++mt) {
                const int pw = pw0 + mt * 16;
                float a0 = xsb[(k0 + tig) * XSP + pw + g];
                float a1 = xsb[(k0 + tig) * XSP + pw + g + 8];
                float a2 = xsb[(k0 + tig + 4) * XSP + pw + g];
                float a3 = xsb[(k0 + tig + 4) * XSP + pw + g + 8];
                asm("cvt.rna.tf32.f32 %0, %1;" : "=r"(ua[mt][0]) : "f"(a0));
                asm("cvt.rna.tf32.f32 %0, %1;" : "=r"(ua[mt][1]) : "f"(a1));
                asm("cvt.rna.tf32.f32 %0, %1;" : "=r"(ua[mt][2]) : "f"(a2));
                asm("cvt.rna.tf32.f32 %0, %1;" : "=r"(ua[mt][3]) : "f"(a3));
            }
            // B fragment pairs via LDS.64 + 4 MMAs each
            const unsigned wrow = smem_u32(wqb + ks * (OALL * 8)) + (unsigned)tig * 8;
#pragma unroll
            for (int nt = 0; nt < 9; ++nt) {
                unsigned b0, b1;
                asm("ld.shared.v2.b32 {%0, %1}, [%2];"
                    : "=r"(b0), "=r"(b1)
                    : "r"(wrow + (unsigned)(nt * 8 + g) * 32));
                mma_tf32(acc[0][nt], ua[0], b0, b1);
                mma_tf32(acc[1][nt], ua[1], b0, b1);
                mma_tf32(acc[2][nt], ua[2], b0, b1);
                mma_tf32(acc[3][nt], ua[3], b0, b1);
            }
        }
        __syncthreads();
    }

    // Epilogue: c0:(g, 2t), c1:(g, 2t+1), c2:(g+8, 2t), c3:(g+8, 2t+1)
#pragma unroll
    for (int mt = 0; mt < 4; ++mt) {
        const int plo = p0 + pw0 + mt * 16 + g;
        const int phi = plo + 8;
        const bool vlo = plo < HW, vhi = phi < HW;
#pragma unroll
        for (int nt = 0; nt < 9; ++nt) {
            const int o0 = nt * 8 + 2 * tig;
            const float bv0 = bsh[o0], bv1 = bsh[o0 + 1];
            float* q0 = out + out_off(o0, b);
            float* q1 = out + out_off(o0 + 1, b);
            if (vlo) {
                q0[plo] = acc[mt][nt][0] + bv0;
                q1[plo] = acc[mt][nt][1] + bv1;
            }
            if (vhi) {
                q0[phi] = acc[mt][nt][2] + bv0;
                q1[phi] = acc[mt][nt][3] + bv1;
            }
        }
    }
}

extern "C" void kernel_launch(void* const* d_in, const int* in_sizes, int n_in,
                              void* d_out, int out_size)
{
    const float *x = nullptr, *wc = nullptr, *bc = nullptr,
                *wr = nullptr, *br = nullptr, *wd = nullptr, *bd = nullptr;
    for (int i = 0; i < n_in; ++i) {
        const float* ptr = (const float*)d_in[i];
        switch (in_sizes[i]) {
            case Bb * Cdim * HW:  x  = ptr; break;
            case Cdim * OCLS:     wc = ptr; break;
            case OCLS:            bc = ptr; break;
            case Cdim * OREG:     wr = ptr; break;
            case OREG:            br = ptr; break;
            case Cdim * ODIR:     wd = ptr; break;
            case ODIR:            bd = ptr; break;
            default: break;
        }
    }

    fuse_kernel<<<(Cdim * OALL + 255) / 256, 256>>>(wc, bc, wr, br, wd, bd);

    cudaFuncSetAttribute(anchor_mma_kernel,
                         cudaFuncAttributeMaxDynamicSharedMemorySize, SM_BYTES);

    dim3 grid((HW + PB - 1) / PB, Bb);   // (210, 4)
    anchor_mma_kernel<<<grid, TPB, SM_BYTES>>>(x, (float*)d_out);
}